// round 17
// baseline (speedup 1.0000x reference)
#include <cuda_runtime.h>
#include <cuda_fp16.h>
#include <math.h>

#define Bn 2
#define Ln 2048
#define Kn 32
#define NF 128

#define HV_OFF   0
#define HE_OFF   (Bn*Ln*NF)                        // 524288
#define EIDX_OFF (HE_OFF + Bn*Ln*Kn*NF)            // 17301504
#define X_OFF    (EIDX_OFF + Bn*Ln*Kn)             // 17432576

// GEMM: 128 edges (4 nodes) per block, K 403 -> 448 (7 chunks of 64 fp16)
#define NCHUNK 7
#define ACH 16384                // A chunk: 128 rows x 128B
#define BCH 16384                // B chunk: 128 rows x 128B

#define NTILE (Ln/128)           // 16
#define NPAIR (NTILE*(NTILE+1)/2) // 136

__device__ int g_eidx[Bn*Ln*Kn];
__device__ __align__(16) unsigned char g_Bhalf[NCHUNK*BCH];  // W fp16, SW128 chunk image
__device__ __align__(16) float4 g_ca[Bn*Ln];                 // packed (Ca.xyz, mask)
__device__ __align__(16) float g_D[(size_t)Bn*Ln*Ln];        // 33.5MB distance matrix (L2-resident)

typedef unsigned long long u64;

#define SWZ(o) ((o) ^ (((o) >> 3) & 0x70))

// ---------- r11-exact math chain (div.full.f32 normalize — passing config) ----------
struct V3 { float x,y,z; };
__device__ __forceinline__ V3 vsub(V3 a, V3 b){
  V3 r; r.x=__fsub_rn(a.x,b.x); r.y=__fsub_rn(a.y,b.y); r.z=__fsub_rn(a.z,b.z); return r;
}
__device__ __forceinline__ V3 cross_x(V3 a, V3 b){
  V3 r;
  r.x = __fmaf_rn(a.y, b.z, -__fmul_rn(a.z, b.y));
  r.y = __fmaf_rn(a.z, b.x, -__fmul_rn(a.x, b.z));
  r.z = __fmaf_rn(a.x, b.y, -__fmul_rn(a.y, b.x));
  return r;
}
__device__ __forceinline__ float dot_x(V3 a, V3 b){
  return __fmaf_rn(a.z, b.z, __fmaf_rn(a.x, b.x, __fmul_rn(a.y, b.y)));
}
__device__ __forceinline__ float n2n(float x){
  if (isnan(x)) return 0.0f;
  if (isinf(x)) return copysignf(3.402823466e38f, x);
  return x;
}
__device__ __forceinline__ float div_full(float a, float b){
  float r; asm("div.full.f32 %0, %1, %2;" : "=f"(r) : "f"(a), "f"(b)); return r;
}
__device__ __forceinline__ V3 norm_x(V3 v){
  float n = __fsqrt_rn(dot_x(v,v));
  V3 r;
  r.x = n2n(div_full(v.x, n));
  r.y = n2n(div_full(v.y, n));
  r.z = n2n(div_full(v.z, n));
  return r;
}
__device__ __forceinline__ float acos_xla(float x){
  if (x == -1.0f) return 3.14159265358979323846f;
  float t = __fmaf_rn(-x, x, 1.0f);
  float s = __fsqrt_rn(t);
  return __fmul_rn(2.0f, atan2f(s, __fadd_rn(1.0f, x)));
}
__device__ __forceinline__ float dihedral(V3 p0, V3 p1, V3 p2, V3 p3){
  V3 u0=vsub(p2,p1), u1=vsub(p0,p1), u2=vsub(p3,p2);
  V3 a=norm_x(cross_x(u0,u1));
  V3 b=norm_x(cross_x(u0,u2));
  float st = dot_x(cross_x(u1,u2), u0);
  float sgn = (st>0.f)?1.f:((st<0.f)?-1.f:0.f);
  float r = __fmul_rn(sgn, acos_xla(dot_x(a,b)));
  if (isnan(r)) r = 0.f;
  return r;
}
__device__ __forceinline__ void comp_cb(const float* p, float* cb){
  float bx=p[3]-p[0], by=p[4]-p[1], bz=p[5]-p[2];
  float cx=p[6]-p[3], cy=p[7]-p[4], cz=p[8]-p[5];
  float ax = by*cz - bz*cy, ay = bz*cx - bx*cz, az = bx*cy - by*cx;
  cb[0] = -0.58273431f*ax + 0.56802827f*bx - 0.54067466f*cx + p[3];
  cb[1] = -0.58273431f*ay + 0.56802827f*by - 0.54067466f*cy + p[4];
  cb[2] = -0.58273431f*az + 0.56802827f*bz - 0.54067466f*cz + p[5];
}
__device__ __forceinline__ unsigned smem_u32(const void* p){
  unsigned a;
  asm("{ .reg .u64 t; cvta.to.shared.u64 t, %1; cvt.u32.u64 %0, t; }" : "=r"(a) : "l"(p));
  return a;
}
__device__ __forceinline__ unsigned redux_min(unsigned v){
  unsigned r; asm("redux.sync.min.u32 %0, %1, 0xffffffff;" : "=r"(r) : "r"(v)); return r;
}

// =====================================================================
// Kernel 0a: W_edge rows 65..467 -> fp16 SW128-chunk image
// =====================================================================
__global__ void wconv_kernel(const float* __restrict__ We){
  int idx = blockIdx.x*256 + threadIdx.x;           // 7*128*64 = 57344
  if (idx >= NCHUNK*128*64) return;
  int c  = idx / (128*64);
  int r  = idx % (128*64);
  int n  = r >> 6;
  int kk = r & 63;
  int kg = c*64 + kk;
  float v = (kg < 403) ? We[(65+kg)*NF + n] : 0.0f;
  unsigned off = ((unsigned)(n>>3)*1024) | ((unsigned)(n&7)*128) | (unsigned)(kk*2);
  *(__half*)(g_Bhalf + c*BCH + SWZ(off)) = __float2half_rn(v);
}

// =====================================================================
// Kernel 0b: pack (Ca.xyz, mask) for coalesced loads
// =====================================================================
__global__ void pack_kernel(const float* __restrict__ X, const float* __restrict__ mask){
  int g = blockIdx.x*256 + threadIdx.x;
  if (g >= Bn*Ln) return;
  g_ca[g] = make_float4(X[(size_t)g*12+3], X[(size_t)g*12+4], X[(size_t)g*12+5], mask[g]);
}

// =====================================================================
// Kernel 1a: symmetric distance tiles (each distance computed ONCE)
// grid = Bn*NPAIR blocks, 256 threads; tile 128x128
// D(i,j) bitwise symmetric: fsub(a,b)=-fsub(b,a); squares equal; fmul comm.
// =====================================================================
__global__ void __launch_bounds__(256) dist_kernel(){
  __shared__ float4 si[128], sj[128];
  int bid = blockIdx.x;
  int b = bid / NPAIR;
  int t = bid % NPAIR;
  int ti = 0;
  while (t >= NTILE - ti){ t -= NTILE - ti; ti++; }
  int tj = ti + t;

  int tid = threadIdx.x;
  if (tid < 128)       si[tid]     = g_ca[b*Ln + ti*128 + tid];
  else                 sj[tid-128] = g_ca[b*Ln + tj*128 + (tid-128)];
  __syncthreads();

  float* Db = g_D + (size_t)b*Ln*Ln;
  int i0 = ti*128, j0 = tj*128;
  #pragma unroll 4
  for (int q=0;q<64;q++){
    int idx = tid + q*256;
    int ii = idx >> 7, jj = idx & 127;
    float4 a = si[ii], c = sj[jj];
    float dx = __fsub_rn(a.x, c.x);
    float dy = __fsub_rn(a.y, c.y);
    float dz = __fsub_rn(a.z, c.z);
    float m2 = __fmul_rn(a.w, c.w);
    float ss = __fadd_rn(
        __fmaf_rn(dz, dz, __fmaf_rn(dx, dx, __fmul_rn(dy, dy))), 1e-6f);
    float D = __fmul_rn(m2, __fsqrt_rn(ss));
    Db[(size_t)(i0+ii)*Ln + (j0+jj)] = D;
    if (ti != tj) Db[(size_t)(j0+jj)*Ln + (i0+ii)] = D;
  }
}

// =====================================================================
// Kernel 1b: per-row top-K selection (register-resident, redux extraction)
// =====================================================================
__global__ void __launch_bounds__(256) select_kernel(
    const float* __restrict__ X, const float* __restrict__ mask,
    float* __restrict__ out)
{
  __shared__ float fred[8];
  __shared__ u64 wtop[8*32];

  int tid = threadIdx.x;
  int g = blockIdx.x;
  int b = g >> 11;
  int i = g & (Ln-1);
  const float* Drow = g_D + (size_t)b*Ln*Ln + (size_t)i*Ln;
  const float* Mrow = mask + b*Ln;
  float mi = mask[g];

  // load 8 D values + 8 mask values (coalesced float4)
  float4 d0 = *(const float4*)(Drow + tid*8);
  float4 d1 = *(const float4*)(Drow + tid*8 + 4);
  float4 m0 = *(const float4*)(Mrow + tid*8);
  float4 m1 = *(const float4*)(Mrow + tid*8 + 4);
  float Dv[8] = {d0.x,d0.y,d0.z,d0.w,d1.x,d1.y,d1.z,d1.w};
  float Mv[8] = {m0.x,m0.y,m0.z,m0.w,m1.x,m1.y,m1.z,m1.w};

  float lmax = 0.0f;
  #pragma unroll
  for (int q=0;q<8;q++) lmax = fmaxf(lmax, Dv[q]);
  #pragma unroll
  for (int o=16;o;o>>=1) lmax = fmaxf(lmax, __shfl_xor_sync(0xffffffffu, lmax, o));
  if ((tid&31)==0) fred[tid>>5] = lmax;
  __syncthreads();
  float Dmax = fred[0];
  #pragma unroll
  for (int q=1;q<8;q++) Dmax = fmaxf(Dmax, fred[q]);

  // D_adj = D + 2*(1-m2)*Dmax, m2 = mi*mask[j]  (exact r16 chain)
  int w = tid >> 5, lane = tid & 31;
  u64 key[8];
  #pragma unroll
  for (int q=0;q<8;q++){
    float m2 = __fmul_rn(mi, Mv[q]);
    float Da = __fadd_rn(Dv[q],
               __fmul_rn(__fmul_rn(2.0f, __fsub_rn(1.0f, m2)), Dmax));
    key[q] = ((u64)__float_as_uint(Da) << 32) | (unsigned)(tid*8 + q);
  }

  // Stage A: per-warp top-32
  for (int k=0;k<Kn;k++){
    u64 m = key[0];
    #pragma unroll
    for (int q=1;q<8;q++) m = (key[q] < m) ? key[q] : m;
    unsigned d32 = (unsigned)(m >> 32);
    unsigned dmin = redux_min(d32);
    unsigned cand = (d32 == dmin) ? (unsigned)m : 0xFFFFFFFFu;
    unsigned imin = redux_min(cand);
    u64 sel = ((u64)dmin << 32) | imin;
    #pragma unroll
    for (int q=0;q<8;q++) if (key[q] == sel) key[q] = ~0ull;
    if (lane==0) wtop[w*32 + k] = sel;
  }
  __syncthreads();

  // Stage B: warp 0 merges 8x32 candidates
  if (w == 0){
    u64 cnd[8];
    #pragma unroll
    for (int q=0;q<8;q++) cnd[q] = wtop[lane*8 + q];
    int base = g*Kn;
    for (int k=0;k<Kn;k++){
      u64 m = cnd[0];
      #pragma unroll
      for (int q=1;q<8;q++) m = (cnd[q] < m) ? cnd[q] : m;
      unsigned d32 = (unsigned)(m >> 32);
      unsigned dmin = redux_min(d32);
      unsigned cand = (d32 == dmin) ? (unsigned)m : 0xFFFFFFFFu;
      unsigned imin = redux_min(cand);
      u64 sel = ((u64)dmin << 32) | imin;
      #pragma unroll
      for (int q=0;q<8;q++) if (cnd[q] == sel) cnd[q] = ~0ull;
      if (lane==0){
        int bj = (int)imin;
        g_eidx[base+k] = bj;
        out[EIDX_OFF + base + k] = (float)bj;
      }
    }
  }
  if (tid < 12) out[X_OFF + (size_t)g*12 + tid] = X[(size_t)g*12 + tid];
}

// =====================================================================
// Kernel 2: node features -> row-lookup GEMM -> LN (unchanged)
// =====================================================================
__global__ void __launch_bounds__(128) node_kernel(
    const int* __restrict__ S, const float* __restrict__ BB, const float* __restrict__ SC,
    const float* __restrict__ Wn, const float* __restrict__ bn,
    const float* __restrict__ gn, const float* __restrict__ betan,
    float* __restrict__ out)
{
  __shared__ float sv[14];
  __shared__ float red1[4];
  __shared__ float red2[4];
  int g = blockIdx.x;
  int f = threadIdx.x;
  if (f < 6) sv[f] = BB[g*6 + f];
  else if (f < 14) sv[f] = SC[g*8 + (f-6)];
  __syncthreads();
  int s = S[g];
  float h = bn[f] + Wn[s*NF + f];
  #pragma unroll
  for (int j=0;j<6;j++)  h = fmaf(sv[j],   Wn[(21+j)*NF + f], h);
  #pragma unroll
  for (int j=0;j<8;j++)  h = fmaf(sv[6+j], Wn[(27+j)*NF + f], h);

  int lane = f & 31, wid = f >> 5;
  float t = h;
  #pragma unroll
  for (int o=16;o;o>>=1) t += __shfl_xor_sync(0xffffffffu, t, o);
  if (lane==0) red1[wid] = t;
  __syncthreads();
  float mean = (red1[0]+red1[1]+red1[2]+red1[3]) * (1.0f/128.0f);
  float d = h - mean;
  float t2 = d*d;
  #pragma unroll
  for (int o=16;o;o>>=1) t2 += __shfl_xor_sync(0xffffffffu, t2, o);
  if (lane==0) red2[wid] = t2;
  __syncthreads();
  float var = (red2[0]+red2[1]+red2[2]+red2[3]) * (1.0f/128.0f);
  out[HV_OFF + (size_t)g*NF + f] = d / sqrtf(var + 1e-5f) * gn[f] + betan[f];
}

// =====================================================================
// Kernel 3: edge features -> fp16 A (two 4-chunk passes) + HMMA + LN
// Block: 4 nodes = 128 edges (M=128), 256 threads, 8 warps. (r16, unchanged)
// =====================================================================
#define SM_X5I   64
#define SM_POS   320
#define SM_A     1024
#define SM_B     (SM_A + 4*ACH)                    // 66560
#define EDGE_SMEM (SM_B + 2*BCH)                   // 99328
#define CSTRIDE  132

__device__ __forceinline__ void prefetch_chunk(unsigned smb, int c, int buf, int tid){
  unsigned dst = smb + SM_B + (unsigned)buf*BCH + (unsigned)tid*16;
  const char* src = (const char*)g_Bhalf + c*BCH + tid*16;
  #pragma unroll
  for (int it=0;it<4;it++)
    asm volatile("cp.async.cg.shared.global [%0], [%1], 16;"
                 :: "r"(dst + it*4096u), "l"(src + it*4096) : "memory");
  asm volatile("cp.async.commit_group;" ::: "memory");
}

__global__ void __launch_bounds__(256, 2) edge_kernel(
    const float* __restrict__ X, const int* __restrict__ chain,
    const float* __restrict__ We, const float* __restrict__ be,
    const float* __restrict__ ge, const float* __restrict__ betae,
    float* __restrict__ out)
{
  extern __shared__ char sm[];
  unsigned smb = smem_u32(sm);
  float* x5i = (float*)(sm + SM_X5I);
  int*   pos = (int*)(sm + SM_POS);

  int tid = threadIdx.x;
  int wid = tid >> 5, lane = tid & 31;
  int g0 = blockIdx.x * 4;
  int b  = g0 >> 11;

  prefetch_chunk(smb, 0, 0, tid);
  prefetch_chunk(smb, 1, 1, tid);

  if (tid < 48){
    int nl = tid / 12, c = tid % 12;
    x5i[nl*15 + c] = X[(size_t)(g0+nl)*12 + c];
  }
  __syncthreads();
  if (tid < 4) comp_cb(x5i + tid*15, x5i + tid*15 + 12);
  __syncthreads();

  int e   = tid >> 1;
  int sub = tid & 1;
  int nl  = e >> 5;
  int k   = e & 31;
  int gi  = g0 + nl;
  int i   = gi & (Ln-1);
  int j   = g_eidx[gi*Kn + k];
  const float* Xb = X + (size_t)b*Ln*12;
  const float* P = x5i + nl*15;
  unsigned rowatom = (unsigned)(e>>3)*1024;
  unsigned rin     = (unsigned)(e&7)*128;

  int mr0 = (wid & 3) * 32;
  int nc0 = (wid >> 2) * 64;
  float acc[2][8][4];
  #pragma unroll
  for (int mt=0;mt<2;mt++)
    #pragma unroll
    for (int nt=0;nt<8;nt++)
      #pragma unroll
      for (int q=0;q<4;q++) acc[mt][nt][q] = 0.f;

  #pragma unroll
  for (int h=0; h<2; h++){
    {
      float n5[15];
      #pragma unroll
      for (int c=0;c<12;c++) n5[c] = Xb[(size_t)j*12 + c];
      comp_cb(n5, n5+12);

      int pstart = h==0 ? sub : 16+sub;
      int pend   = h==0 ? 16 : 25;
      for (int p = pstart; p < pend; p += 2){
        int a = p/5, q = p%5;
        float dx = P[a*3+0]-n5[q*3+0];
        float dy = P[a*3+1]-n5[q*3+1];
        float dz = P[a*3+2]-n5[q*3+2];
        float d = sqrtf(dx*dx + dy*dy + dz*dz + 1e-6f);
        unsigned h2[8];
        #pragma unroll
        for (int r2=0;r2<8;r2++){
          float mu0 = (float)(2*r2)   * (20.0f/15.0f);
          float mu1 = (float)(2*r2+1) * (20.0f/15.0f);
          float t0 = (d - mu0) * 0.8f;
          float t1 = (d - mu1) * 0.8f;
          __half2 hh = __floats2half2_rn(__expf(-t0*t0), __expf(-t1*t1));
          h2[r2] = *(unsigned*)&hh;
        }
        int cb2 = (p >> 2) - h*4;
        unsigned kb = (unsigned)(p&3)*32;
        char* base = sm + SM_A + cb2*ACH + rowatom;
        *(uint4*)(base + SWZ(rin + kb))      = make_uint4(h2[0],h2[1],h2[2],h2[3]);
        *(uint4*)(base + SWZ(rin + kb + 16)) = make_uint4(h2[4],h2[5],h2[6],h2[7]);
      }
      if (h==1 && sub == 1){
        float et = (chain[b*Ln + j] == chain[gi]) ? 2.0f : 1.0f;
        V3 Ni  = {P[0],P[1],P[2]},  Cai = {P[3],P[4],P[5]},  Ci = {P[6],P[7],P[8]};
        V3 Nj  = {n5[0],n5[1],n5[2]}, Caj = {n5[3],n5[4],n5[5]}, Cj = {n5[6],n5[7],n5[8]};
        float d0 = dihedral(Ci, Nj, Caj, Cj);
        float d1 = dihedral(Ni, Cai, Ci, Nj);
        __half2 hh0 = __floats2half2_rn(et, d0);
        __half2 hh1 = __floats2half2_rn(d1, 0.f);
        char* base = sm + SM_A + 2*ACH + rowatom;
        *(uint4*)(base + SWZ(rin + 32)) = make_uint4(*(unsigned*)&hh0, *(unsigned*)&hh1, 0u, 0u);
        #pragma unroll
        for (int s4=1;s4<6;s4++)
          *(uint4*)(base + SWZ(rin + 32 + (unsigned)s4*16)) = make_uint4(0u,0u,0u,0u);
        int offp = j - i + 32;
        pos[e] = min(max(offp, 0), 64);
      }
    }
    __syncthreads();

    int cend = h==0 ? 4 : NCHUNK;
    for (int c = h*4; c < cend; c++){
      if (c == NCHUNK-1) asm volatile("cp.async.wait_group 0;" ::: "memory");
      else               asm volatile("cp.async.wait_group 1;" ::: "memory");
      __syncthreads();
      unsigned CA = smb + SM_A + (unsigned)(c - h*4)*ACH;
      unsigned CB = smb + SM_B + (unsigned)(c&1)*BCH;
      #pragma unroll
      for (int ks = 0; ks < 4; ks++){
        unsigned kb = (unsigned)ks*32;
        unsigned af[2][4];
        #pragma unroll
        for (int mt=0;mt<2;mt++){
          int r = mr0 + mt*16 + (lane & 15);
          unsigned sel = (unsigned)(lane >> 4) * 16;
          unsigned addr = CA + (unsigned)(r>>3)*1024 + SWZ((unsigned)(r&7)*128 + kb + sel);
          asm volatile("ldmatrix.sync.aligned.m8n8.x4.shared.b16 {%0,%1,%2,%3}, [%4];"
            : "=r"(af[mt][0]), "=r"(af[mt][1]), "=r"(af[mt][2]), "=r"(af[mt][3]) : "r"(addr));
        }
        unsigned bf[8][2];
        #pragma unroll
        for (int ntp=0;ntp<4;ntp++){
          int col = nc0 + ntp*16 + ((lane >> 4) << 3) + (lane & 7);
          unsigned khalf = (unsigned)((lane >> 3) & 1) * 16;
          unsigned addr = CB + (unsigned)(col>>3)*1024 + SWZ((unsigned)(col&7)*128 + kb + khalf);
          asm volatile("ldmatrix.sync.aligned.m8n8.x4.shared.b16 {%0,%1,%2,%3}, [%4];"
            : "=r"(bf[2*ntp][0]), "=r"(bf[2*ntp][1]), "=r"(bf[2*ntp+1][0]), "=r"(bf[2*ntp+1][1])
            : "r"(addr));
        }
        #pragma unroll
        for (int mt=0;mt<2;mt++)
          #pragma unroll
          for (int nt=0;nt<8;nt++)
            asm volatile(
              "mma.sync.aligned.m16n8k16.row.col.f32.f16.f16.f32 "
              "{%0,%1,%2,%3}, {%4,%5,%6,%7}, {%8,%9}, {%0,%1,%2,%3};"
              : "+f"(acc[mt][nt][0]), "+f"(acc[mt][nt][1]),
                "+f"(acc[mt][nt][2]), "+f"(acc[mt][nt][3])
              : "r"(af[mt][0]), "r"(af[mt][1]), "r"(af[mt][2]), "r"(af[mt][3]),
                "r"(bf[nt][0]), "r"(bf[nt][1]));
      }
      __syncthreads();
      if (c+2 < NCHUNK) prefetch_chunk(smb, c+2, c&1, tid);
    }
  }

  {
    float* C = (float*)(sm + SM_A);
    #pragma unroll
    for (int mt=0;mt<2;mt++)
      #pragma unroll
      for (int nt=0;nt<8;nt++){
        int row = mr0 + mt*16 + (lane >> 2);
        int col = nc0 + nt*8 + 2*(lane & 3);
        C[row*CSTRIDE + col]       = acc[mt][nt][0];
        C[row*CSTRIDE + col + 1]   = acc[mt][nt][1];
        C[(row+8)*CSTRIDE + col]   = acc[mt][nt][2];
        C[(row+8)*CSTRIDE + col+1] = acc[mt][nt][3];
      }
  }
  __syncthreads();

  {
    const float* C = (const float*)(sm + SM_A);
    int row = tid >> 1, seg = tid & 1;
    const float* Wrow = We + (size_t)pos[row]*NF;
    float sum = 0.f, sumsq = 0.f;
    #pragma unroll
    for (int q=0;q<64;q++){
      int f = seg*64 + q;
      float v = C[row*CSTRIDE + f] + be[f] + Wrow[f];
      sum += v; sumsq += v*v;
    }
    sum   += __shfl_xor_sync(0xffffffffu, sum, 1);
    sumsq += __shfl_xor_sync(0xffffffffu, sumsq, 1);
    float mean = sum * (1.0f/128.0f);
    float var  = sumsq * (1.0f/128.0f) - mean*mean;
    float inv  = 1.0f / sqrtf(var + 1e-5f);

    int nl2 = row >> 5, k2 = row & 31;
    float* O = out + HE_OFF + ((size_t)(g0+nl2)*Kn + k2)*NF + seg*64;
    #pragma unroll
    for (int q=0;q<64;q+=4){
      int f = seg*64 + q;
      float4 o4;
      o4.x = (C[row*CSTRIDE+f]   + be[f]   + Wrow[f]   - mean)*inv*ge[f]   + betae[f];
      o4.y = (C[row*CSTRIDE+f+1] + be[f+1] + Wrow[f+1] - mean)*inv*ge[f+1] + betae[f+1];
      o4.z = (C[row*CSTRIDE+f+2] + be[f+2] + Wrow[f+2] - mean)*inv*ge[f+2] + betae[f+2];
      o4.w = (C[row*CSTRIDE+f+3] + be[f+3] + Wrow[f+3] - mean)*inv*ge[f+3] + betae[f+3];
      *(float4*)(O + q) = o4;
    }
  }
}

extern "C" void kernel_launch(void* const* d_in, const int* in_sizes, int n_in,
                              void* d_out, int out_size) {
  (void)in_sizes; (void)n_in; (void)out_size;
  const float* X     = (const float*)d_in[0];
  const int*   S     = (const int*)  d_in[1];
  const float* BB    = (const float*)d_in[2];
  const float* SC    = (const float*)d_in[3];
  const int*   chain = (const int*)  d_in[4];
  const float* mask  = (const float*)d_in[5];
  const float* Wn    = (const float*)d_in[6];
  const float* bn    = (const float*)d_in[7];
  const float* gn    = (const float*)d_in[8];
  const float* betan = (const float*)d_in[9];
  const float* We    = (const float*)d_in[10];
  const float* be    = (const float*)d_in[11];
  const float* ge    = (const float*)d_in[12];
  const float* betae = (const float*)d_in[13];
  float* out = (float*)d_out;

  cudaFuncSetAttribute(edge_kernel, cudaFuncAttributeMaxDynamicSharedMemorySize, EDGE_SMEM);

  pack_kernel  <<<(Bn*Ln + 255)/256, 256>>>(X, mask);
  wconv_kernel <<<(NCHUNK*128*64 + 255)/256, 256>>>(We);
  dist_kernel  <<<Bn*NPAIR, 256>>>();
  select_kernel<<<Bn*Ln, 256>>>(X, mask, out);
  node_kernel  <<<Bn*Ln, 128>>>(S, BB, SC, Wn, bn, gn, betan, out);
  edge_kernel  <<<Bn*Ln/4, 256, EDGE_SMEM>>>(X, chain, We, be, ge, betae, out);
}